// round 5
// baseline (speedup 1.0000x reference)
#include <cuda_runtime.h>
#include <cstdint>

#define B_  8
#define C_  21
#define D_  64
#define O_  128
#define HW_ 65536
#define N_TOT (B_ * HW_)

typedef unsigned long long ull;
typedef unsigned int uint;

#define FFMA2(acc, a, b) asm("fma.rn.f32x2 %0, %1, %2, %0;" : "+l"(acc) : "l"(a), "l"(b))
#define FADD2(acc, a)    asm("add.rn.f32x2 %0, %0, %1;"     : "+l"(acc) : "l"(a))

// ---------------- device scratch ---------------------------------------------
#define KS_CHUNKS 32
#define NVAL 462                      // 441 gram + 21 sums
__device__ float g_Gp[KS_CHUNKS * B_ * NVAL];   // per-block stat partials
__device__ float g_W2T[B_ * C_ * O_];           // combined weights [b][c][o]
__device__ ull   g_A2[B_ * C_ * O_];            // alpha*W2, f32x2-dup, [b][c][o]
__device__ ull   g_bias2[O_];                   // fused bias, f32x2-dup

// ---------------- cp.async helpers -------------------------------------------
__device__ __forceinline__ void cp16(void* dst, const void* src) {
    uint s = (uint)__cvta_generic_to_shared(dst);
    asm volatile("cp.async.cg.shared.global [%0], [%1], 16;" :: "r"(s), "l"(src));
}
#define CP_COMMIT() asm volatile("cp.async.commit_group;" ::: "memory")
#define CP_WAIT1()  asm volatile("cp.async.wait_group 1;" ::: "memory")
#define CP_WAIT0()  asm volatile("cp.async.wait_group 0;" ::: "memory")

__device__ __forceinline__ float pairsum(ull a) {
    return __uint_as_float((uint)(a & 0xffffffffu)) + __uint_as_float((uint)(a >> 32));
}

// ---------------- kstats: mask sums + Gram, packed f32x2 ----------------------
// grid (32, 8): x = 2048-px chunk, y = batch. 384 threads = 12 warps (balanced).
// Warp w owns Gram rows: w<9 ? {2w, 2w+1} : {18 + (w-9)}. Accumulators are
// packed pixel-pairs (fma.rn.f32x2). Mask staged once via cp.async dbl-buffer.
#define KS_TILE 256
#define KS_NT   8

__global__ __launch_bounds__(384, 1) void kstats(const float* __restrict__ mask) {
    __shared__ __align__(16) float sT[2][C_][KS_TILE];   // 43008 B

    const int b = blockIdx.y;
    const int chunk = blockIdx.x;
    const int tid = threadIdx.x;
    const int wid = tid >> 5;
    const int lane = tid & 31;
    const int nr = (wid < 9) ? 2 : 1;
    const int r0 = (wid < 9) ? wid * 2 : 18 + (wid - 9);

    const float* mb = mask + (size_t)b * C_ * HW_ + chunk * (KS_TILE * KS_NT);

    auto issue = [&](int t) {
        const float* src0 = mb + t * KS_TILE;
        for (int u = tid; u < C_ * (KS_TILE / 4); u += 384) {
            int c = u >> 6, q = u & 63;
            cp16(&sT[t & 1][c][q * 4], src0 + (size_t)c * HW_ + q * 4);
        }
        CP_COMMIT();
    };

    ull acc[2][C_];
    ull ss[2] = {0ull, 0ull};
#pragma unroll
    for (int i = 0; i < 2; i++)
#pragma unroll
        for (int c = 0; c < C_; c++) acc[i][c] = 0ull;

    issue(0);
    for (int t = 0; t < KS_NT; t++) {
        if (t + 1 < KS_NT) { issue(t + 1); CP_WAIT1(); } else { CP_WAIT0(); }
        __syncthreads();
        const int buf = t & 1;
#pragma unroll
        for (int sub = 0; sub < 4; sub++) {
            const int pr = sub * 32 + lane;
            ull mp[C_];
#pragma unroll
            for (int c = 0; c < C_; c++)
                mp[c] = reinterpret_cast<const ull*>(sT[buf][c])[pr];
#pragma unroll
            for (int i = 0; i < 2; i++) {
                if (i < nr) {
                    const ull mr = mp[r0 + i];
                    FADD2(ss[i], mr);
#pragma unroll
                    for (int c = 0; c < C_; c++) FFMA2(acc[i][c], mr, mp[c]);
                }
            }
        }
        __syncthreads();
    }

    // row-exclusive reduce: shfl to lane 0, direct partial writes
    float* gp = g_Gp + (chunk * B_ + b) * NVAL;
#pragma unroll
    for (int i = 0; i < 2; i++) {
        if (i < nr) {
#pragma unroll
            for (int c = 0; c < C_; c++) {
                float v = pairsum(acc[i][c]);
#pragma unroll
                for (int off = 16; off; off >>= 1) v += __shfl_xor_sync(0xffffffffu, v, off);
                if (lane == 0) gp[(r0 + i) * C_ + c] = v;
            }
            float v = pairsum(ss[i]);
#pragma unroll
            for (int off = 16; off; off >>= 1) v += __shfl_xor_sync(0xffffffffu, v, off);
            if (lane == 0) gp[441 + r0 + i] = v;
        }
    }
}

// ---------------- kprep1: W2T[b][c][o] = <conv_w[o,:], feat[b,c,:]> ----------
__global__ __launch_bounds__(256) void kprep1(const float* __restrict__ feat,
                                              const float* __restrict__ conv_w) {
    __shared__ float sWT[D_ * 129 + 32];
    __shared__ float sF[C_ * D_];
    const int b = blockIdx.x;
    const int tid = threadIdx.x;

    for (int i = tid; i < O_ * D_; i += 256) {
        int o = i >> 6, d = i & 63;
        sWT[d * 129 + o] = conv_w[i];
    }
    for (int i = tid; i < C_ * D_; i += 256) sF[i] = feat[b * C_ * D_ + i];
    __syncthreads();

    for (int idx = tid; idx < C_ * O_; idx += 256) {
        int c = idx >> 7, o = idx & 127;
        float s = 0.f;
#pragma unroll
        for (int d = 0; d < D_; d++)
            s = fmaf(sWT[d * 129 + o], sF[c * D_ + d], s);
        g_W2T[b * C_ * O_ + idx] = s;
    }
}

// ---------------- kprep2: reduce partials, analytic BN, fused coeffs ---------
__global__ __launch_bounds__(256) void kprep2(const float* __restrict__ conv_b,
                                              const float* __restrict__ gamma,
                                              const float* __restrict__ beta) {
    __shared__ float salpha[O_];
    __shared__ float sG[B_ * 441];
    __shared__ float sS[B_ * C_];
    const int tid = threadIdx.x;

    for (int idx = tid; idx < B_ * NVAL; idx += 256) {
        int b = idx / NVAL, v = idx - b * NVAL;
        float s = 0.f;
#pragma unroll
        for (int ch = 0; ch < KS_CHUNKS; ch++) s += g_Gp[(ch * B_ + b) * NVAL + v];
        if (v < 441) sG[b * 441 + v] = s;
        else         sS[b * C_ + (v - 441)] = s;
    }
    __syncthreads();

    if (tid < O_) {
        const int o = tid;
        float sumY = 0.f, sumQ = 0.f;
#pragma unroll 1
        for (int b = 0; b < B_; b++) {
            float w[C_];
#pragma unroll
            for (int c = 0; c < C_; c++) w[c] = g_W2T[(b * C_ + c) * O_ + o];
#pragma unroll
            for (int c = 0; c < C_; c++) sumY = fmaf(w[c], sS[b * C_ + c], sumY);
#pragma unroll
            for (int c = 0; c < C_; c++) {
                float t = 0.f;
#pragma unroll
                for (int c2 = 0; c2 < C_; c2++)
                    t = fmaf(w[c2], sG[b * 441 + c * C_ + c2], t);
                sumQ = fmaf(w[c], t, sumQ);
            }
        }
        const float invN = 1.f / (float)N_TOT;
        const float b0 = conv_b[o];
        const float es = sumY * invN;
        const float mean = b0 + es;
        const float ey2 = sumQ * invN + 2.f * b0 * es + b0 * b0;
        const float var = ey2 - mean * mean;
        const float alpha = gamma[o] * rsqrtf(var + 1e-5f);
        salpha[o] = alpha;
        const float bias2 = beta[o] + alpha * (b0 - mean);
        const uint ub = __float_as_uint(bias2);
        g_bias2[o] = ((ull)ub << 32) | ub;
    }
    __syncthreads();

    for (int idx = tid; idx < B_ * C_ * O_; idx += 256) {
        float v = salpha[idx & 127] * g_W2T[idx];
        uint uv = __float_as_uint(v);
        g_A2[idx] = ((ull)uv << 32) | uv;
    }
}

// ---------------- kmain: persistent fused K=21 GEMM + BN + ReLU --------------
// 296 blocks x 512 threads (2 blocks/SM -> 32 warps/SM, 100% occ target).
// Warp = 8 channels; thread = 1 quad (4 px) x 8 channels (acc = 16 ull).
// Per c: 1 mask LDS.128 + 4 coef LDS.128 (broadcast) + 16 FFMA2.
#define KM_NBLK 296
#define KM_NT   4096
#define KM_PX   128

__global__ __launch_bounds__(512, 2) void kmain(const float* __restrict__ mask,
                                                float* __restrict__ out) {
    __shared__ ull sA2[C_ * O_];                       // 21504 B
    __shared__ ull sBias[O_];                          // 1024 B
    __shared__ __align__(16) float sM[2][C_][KM_PX];   // 21504 B  (total 44 KB)

    const int tid = threadIdx.x;
    const int wid = tid >> 5;
    const int lane = tid & 31;
    const int o0 = wid * 8;

    const int bid = blockIdx.x;
    const int t0 = (bid * KM_NT) / KM_NBLK;
    const int t1 = ((bid + 1) * KM_NT) / KM_NBLK;

    if (tid < O_) sBias[tid] = g_bias2[tid];

    auto issue = [&](int s, int buf) {
        const int b = s >> 9;
        const int px = (s & 511) * KM_PX;
        const float* mb = mask + (size_t)b * C_ * HW_ + px;
        for (int u = tid; u < C_ * (KM_PX / 4); u += 512) {   // 672 units
            int c = u >> 5, q = u & 31;
            cp16(&sM[buf][c][q * 4], mb + (size_t)c * HW_ + q * 4);
        }
        CP_COMMIT();
    };
    auto stage = [&](int b) {
        for (int i = tid; i < C_ * O_; i += 512) sA2[i] = g_A2[b * C_ * O_ + i];
    };

    int curb = t0 >> 9;
    issue(t0, 0);
    stage(curb);

#pragma unroll 1
    for (int s = t0; s < t1; s++) {
        const int buf = (s - t0) & 1;
        if (s + 1 < t1) { issue(s + 1, buf ^ 1); CP_WAIT1(); } else { CP_WAIT0(); }
        const int b = s >> 9;
        if (b != curb) { __syncthreads(); stage(b); curb = b; }
        __syncthreads();

        ull acc[8][2];
#pragma unroll
        for (int j = 0; j < 8; j++) {
            ull bv = sBias[o0 + j];
            acc[j][0] = bv; acc[j][1] = bv;
        }

#pragma unroll
        for (int c = 0; c < C_; c++) {
            ulonglong2 mq = reinterpret_cast<const ulonglong2*>(sM[buf][c])[lane];
            const ulonglong2* cfp = reinterpret_cast<const ulonglong2*>(&sA2[c * O_ + o0]);
#pragma unroll
            for (int k = 0; k < 4; k++) {
                ulonglong2 cf = cfp[k];      // warp-uniform broadcast LDS.128
                FFMA2(acc[2 * k][0],     cf.x, mq.x);
                FFMA2(acc[2 * k][1],     cf.x, mq.y);
                FFMA2(acc[2 * k + 1][0], cf.y, mq.x);
                FFMA2(acc[2 * k + 1][1], cf.y, mq.y);
            }
        }
        __syncthreads();   // release sM[buf] before refill

        // epilogue: ReLU + STG.128
        const int px = (s & 511) * KM_PX;
        float* ob = out + (size_t)b * O_ * HW_ + px;
#pragma unroll
        for (int j = 0; j < 8; j++) {
            ull a0 = acc[j][0], a1 = acc[j][1];
            float4 v = make_float4(
                fmaxf(__uint_as_float((uint)(a0 & 0xffffffffu)), 0.f),
                fmaxf(__uint_as_float((uint)(a0 >> 32)),         0.f),
                fmaxf(__uint_as_float((uint)(a1 & 0xffffffffu)), 0.f),
                fmaxf(__uint_as_float((uint)(a1 >> 32)),         0.f));
            reinterpret_cast<float4*>(ob + (size_t)(o0 + j) * HW_)[lane] = v;
        }
    }
}

// ---------------- launcher ----------------------------------------------------
extern "C" void kernel_launch(void* const* d_in, const int* in_sizes, int n_in,
                              void* d_out, int out_size) {
    const float* feat   = (const float*)d_in[0];
    const float* mask   = (const float*)d_in[1];
    const float* conv_w = (const float*)d_in[2];
    const float* conv_b = (const float*)d_in[3];
    const float* gamma  = (const float*)d_in[4];
    const float* beta   = (const float*)d_in[5];
    float* out = (float*)d_out;

    kstats<<<dim3(KS_CHUNKS, B_), 384>>>(mask);
    kprep1<<<B_, 256>>>(feat, conv_w);
    kprep2<<<1, 256>>>(conv_b, gamma, beta);
    kmain<<<KM_NBLK, 512>>>(mask, out);
}

// round 6
// speedup vs baseline: 1.3155x; 1.3155x over previous
#include <cuda_runtime.h>
#include <cstdint>

#define B_  8
#define C_  21
#define D_  64
#define O_  128
#define HW_ 65536
#define N_TOT (B_ * HW_)

typedef unsigned long long ull;
typedef unsigned int uint;

#define FFMA2(acc, a, b) asm("fma.rn.f32x2 %0, %1, %2, %0;" : "+l"(acc) : "l"(a), "l"(b))
#define FADD2(acc, a)    asm("add.rn.f32x2 %0, %0, %1;"     : "+l"(acc) : "l"(a))

// ---------------- device scratch ---------------------------------------------
#define KS_CHUNKS 64
#define NVAL 462                      // 441 gram + 21 sums
__device__ float g_Gp[KS_CHUNKS * B_ * NVAL];   // per-block stat partials
__device__ float g_Gred[B_ * NVAL];             // reduced stats
__device__ float g_W2T[B_ * C_ * O_];           // combined weights [b][c][o]
__device__ ull   g_A2[B_ * C_ * O_];            // alpha*W2, f32x2-dup, [b][c][o]
__device__ ull   g_bias2[O_];                   // fused bias, f32x2-dup

// ---------------- cp.async helpers -------------------------------------------
__device__ __forceinline__ void cp16(void* dst, const void* src) {
    uint s = (uint)__cvta_generic_to_shared(dst);
    asm volatile("cp.async.cg.shared.global [%0], [%1], 16;" :: "r"(s), "l"(src));
}
#define CP_COMMIT() asm volatile("cp.async.commit_group;" ::: "memory")
#define CP_WAIT1()  asm volatile("cp.async.wait_group 1;" ::: "memory")
#define CP_WAIT0()  asm volatile("cp.async.wait_group 0;" ::: "memory")

__device__ __forceinline__ float pairsum(ull a) {
    return __uint_as_float((uint)(a & 0xffffffffu)) + __uint_as_float((uint)(a >> 32));
}
__device__ __forceinline__ ull lo64(float4 v) {
    return ((ull)__float_as_uint(v.y) << 32) | __float_as_uint(v.x);
}
__device__ __forceinline__ ull hi64(float4 v) {
    return ((ull)__float_as_uint(v.w) << 32) | __float_as_uint(v.z);
}

// ---------------- kstats: streaming LDG Gram, no smem, no spills -------------
// grid (64, 8): x = 1024-px chunk, y = batch. 384 threads = 12 warps.
// Warp w<9 owns rows {2w, 2w+1}; w in [9,12) owns row {18+(w-9)}.
// Each warp streams the 21xTile columns as float4; own rows loaded first.
// Register budget: acc 84 + mr 8 + small streaming window -> no spills.
__global__ __launch_bounds__(384) void kstats(const float* __restrict__ mask) {
    const int b = blockIdx.y;
    const int chunk = blockIdx.x;
    const int tid = threadIdx.x;
    const int wid = tid >> 5;
    const int lane = tid & 31;
    const int nr = (wid < 9) ? 2 : 1;
    const int r0 = (wid < 9) ? wid * 2 : 18 + (wid - 9);

    const float* mb = mask + (size_t)b * C_ * HW_ + chunk * 1024;

    ull acc[2][C_];
    ull ss[2] = {0ull, 0ull};
#pragma unroll
    for (int i = 0; i < 2; i++)
#pragma unroll
        for (int c = 0; c < C_; c++) acc[i][c] = 0ull;

#pragma unroll 1
    for (int it = 0; it < 8; it++) {
        const int q = it * 32 + lane;             // float4 index within 1024-px tile
        // own rows first
        float4 r0v = reinterpret_cast<const float4*>(mb + (size_t)(r0) * HW_)[q];
        ull mr0a = lo64(r0v), mr0b = hi64(r0v);
        FADD2(ss[0], mr0a); FADD2(ss[0], mr0b);
        ull mr1a = 0, mr1b = 0;
        if (nr == 2) {
            float4 r1v = reinterpret_cast<const float4*>(mb + (size_t)(r0 + 1) * HW_)[q];
            mr1a = lo64(r1v); mr1b = hi64(r1v);
            FADD2(ss[1], mr1a); FADD2(ss[1], mr1b);
        }
        // stream all 21 columns, FFMA2 immediately (no mp[] array)
#pragma unroll
        for (int c = 0; c < C_; c++) {
            float4 v = reinterpret_cast<const float4*>(mb + (size_t)c * HW_)[q];
            ull va = lo64(v), vb = hi64(v);
            FFMA2(acc[0][c], mr0a, va);
            FFMA2(acc[0][c], mr0b, vb);
            if (nr == 2) {
                FFMA2(acc[1][c], mr1a, va);
                FFMA2(acc[1][c], mr1b, vb);
            }
        }
    }

    // row-exclusive reduce: shfl to lane 0, direct partial writes
    float* gp = g_Gp + (chunk * B_ + b) * NVAL;
#pragma unroll
    for (int i = 0; i < 2; i++) {
        if (i < nr) {
#pragma unroll
            for (int c = 0; c < C_; c++) {
                float v = pairsum(acc[i][c]);
#pragma unroll
                for (int off = 16; off; off >>= 1) v += __shfl_xor_sync(0xffffffffu, v, off);
                if (lane == 0) gp[(r0 + i) * C_ + c] = v;
            }
            float v = pairsum(ss[i]);
#pragma unroll
            for (int off = 16; off; off >>= 1) v += __shfl_xor_sync(0xffffffffu, v, off);
            if (lane == 0) gp[441 + r0 + i] = v;
        }
    }
}

// ---------------- kred: reduce 64 chunk-partials -> g_Gred -------------------
// grid (8), 256 threads
__global__ __launch_bounds__(256) void kred() {
    const int b = blockIdx.x;
    for (int v = threadIdx.x; v < NVAL; v += 256) {
        float s = 0.f;
#pragma unroll
        for (int ch = 0; ch < KS_CHUNKS; ch++) s += g_Gp[(ch * B_ + b) * NVAL + v];
        g_Gred[b * NVAL + v] = s;
    }
}

// ---------------- kprep1: W2T[b][c][o] = <conv_w[o,:], feat[b,c,:]> ----------
__global__ __launch_bounds__(256) void kprep1(const float* __restrict__ feat,
                                              const float* __restrict__ conv_w) {
    __shared__ float sWT[D_ * 129 + 32];
    __shared__ float sF[C_ * D_];
    const int b = blockIdx.x;
    const int tid = threadIdx.x;

    for (int i = tid; i < O_ * D_; i += 256) {
        int o = i >> 6, d = i & 63;
        sWT[d * 129 + o] = conv_w[i];
    }
    for (int i = tid; i < C_ * D_; i += 256) sF[i] = feat[b * C_ * D_ + i];
    __syncthreads();

    for (int idx = tid; idx < C_ * O_; idx += 256) {
        int c = idx >> 7, o = idx & 127;
        float s = 0.f;
#pragma unroll
        for (int d = 0; d < D_; d++)
            s = fmaf(sWT[d * 129 + o], sF[c * D_ + d], s);
        g_W2T[b * C_ * O_ + idx] = s;
    }
}

// ---------------- kprep2: analytic BN, fused coefficients --------------------
__global__ __launch_bounds__(256) void kprep2(const float* __restrict__ conv_b,
                                              const float* __restrict__ gamma,
                                              const float* __restrict__ beta) {
    __shared__ float salpha[O_];
    __shared__ float sG[B_ * 441];
    __shared__ float sS[B_ * C_];
    const int tid = threadIdx.x;

    for (int idx = tid; idx < B_ * NVAL; idx += 256) {
        int b = idx / NVAL, v = idx - b * NVAL;
        float s = g_Gred[b * NVAL + v];
        if (v < 441) sG[b * 441 + v] = s;
        else         sS[b * C_ + (v - 441)] = s;
    }
    __syncthreads();

    if (tid < O_) {
        const int o = tid;
        float sumY = 0.f, sumQ = 0.f;
#pragma unroll 1
        for (int b = 0; b < B_; b++) {
            float w[C_];
#pragma unroll
            for (int c = 0; c < C_; c++) w[c] = g_W2T[(b * C_ + c) * O_ + o];
#pragma unroll
            for (int c = 0; c < C_; c++) sumY = fmaf(w[c], sS[b * C_ + c], sumY);
#pragma unroll
            for (int c = 0; c < C_; c++) {
                float t = 0.f;
#pragma unroll
                for (int c2 = 0; c2 < C_; c2++)
                    t = fmaf(w[c2], sG[b * 441 + c * C_ + c2], t);
                sumQ = fmaf(w[c], t, sumQ);
            }
        }
        const float invN = 1.f / (float)N_TOT;
        const float b0 = conv_b[o];
        const float es = sumY * invN;
        const float mean = b0 + es;
        const float ey2 = sumQ * invN + 2.f * b0 * es + b0 * b0;
        const float var = ey2 - mean * mean;
        const float alpha = gamma[o] * rsqrtf(var + 1e-5f);
        salpha[o] = alpha;
        const float bias2 = beta[o] + alpha * (b0 - mean);
        const uint ub = __float_as_uint(bias2);
        g_bias2[o] = ((ull)ub << 32) | ub;
    }
    __syncthreads();

    for (int idx = tid; idx < B_ * C_ * O_; idx += 256) {
        float v = salpha[idx & 127] * g_W2T[idx];
        uint uv = __float_as_uint(v);
        g_A2[idx] = ((ull)uv << 32) | uv;
    }
}

// ---------------- kmain: persistent fused K=21 GEMM + BN + ReLU --------------
// 296 blocks x 256 threads (2 blocks/SM). Subtile = 128 px x 128 ch.
// 8 warps; warp = 16 channels; thread = 1 quad (4 px) x 16 channels.
// Per c per warp: 1 mask LDS.128 (4 phases) + 8 coef LDS.128 broadcast
// (8 phases) vs 32 FFMA2 (16 SM-cyc) -> FMA-bound.
#define KM_NBLK 296
#define KM_NT   4096
#define KM_PX   128

__global__ __launch_bounds__(256) void kmain(const float* __restrict__ mask,
                                             float* __restrict__ out) {
    __shared__ ull sA2[C_ * O_];                       // 21504 B
    __shared__ ull sBias[O_];                          // 1024 B
    __shared__ __align__(16) float sM[2][C_][KM_PX];   // 21504 B  (44 KB total)

    const int tid = threadIdx.x;
    const int wid = tid >> 5;
    const int lane = tid & 31;
    const int o0 = wid * 16;

    const int bid = blockIdx.x;
    const int t0 = (bid * KM_NT) / KM_NBLK;
    const int t1 = ((bid + 1) * KM_NT) / KM_NBLK;

    if (tid < O_) sBias[tid] = g_bias2[tid];

    auto issue = [&](int s, int buf) {
        const int b = s >> 9;
        const int px = (s & 511) * KM_PX;
        const float* mb = mask + (size_t)b * C_ * HW_ + px;
        for (int u = tid; u < C_ * (KM_PX / 4); u += 256) {   // 672 units
            int c = u >> 5, q = u & 31;
            cp16(&sM[buf][c][q * 4], mb + (size_t)c * HW_ + q * 4);
        }
        CP_COMMIT();
    };
    auto stage = [&](int b) {
        for (int i = tid; i < C_ * O_; i += 256) sA2[i] = g_A2[b * C_ * O_ + i];
    };

    int curb = t0 >> 9;
    issue(t0, 0);
    stage(curb);

#pragma unroll 1
    for (int s = t0; s < t1; s++) {
        const int buf = (s - t0) & 1;
        if (s + 1 < t1) { issue(s + 1, buf ^ 1); CP_WAIT1(); } else { CP_WAIT0(); }
        const int b = s >> 9;
        if (b != curb) { __syncthreads(); stage(b); curb = b; }
        __syncthreads();

        ull acc[16][2];
#pragma unroll
        for (int j = 0; j < 16; j++) {
            ull bv = sBias[o0 + j];
            acc[j][0] = bv; acc[j][1] = bv;
        }

#pragma unroll
        for (int c = 0; c < C_; c++) {
            ulonglong2 mq = reinterpret_cast<const ulonglong2*>(sM[buf][c])[lane];
            const ulonglong2* cfp = reinterpret_cast<const ulonglong2*>(&sA2[c * O_ + o0]);
#pragma unroll
            for (int k = 0; k < 8; k++) {
                ulonglong2 cf = cfp[k];      // warp-uniform broadcast LDS.128
                FFMA2(acc[2 * k][0],     cf.x, mq.x);
                FFMA2(acc[2 * k][1],     cf.x, mq.y);
                FFMA2(acc[2 * k + 1][0], cf.y, mq.x);
                FFMA2(acc[2 * k + 1][1], cf.y, mq.y);
            }
        }
        __syncthreads();   // release sM[buf] before refill

        // epilogue: ReLU + STG.128
        const int px = (s & 511) * KM_PX;
        float* ob = out + (size_t)b * O_ * HW_ + px;
#pragma unroll
        for (int j = 0; j < 16; j++) {
            ull a0 = acc[j][0], a1 = acc[j][1];
            float4 v = make_float4(
                fmaxf(__uint_as_float((uint)(a0 & 0xffffffffu)), 0.f),
                fmaxf(__uint_as_float((uint)(a0 >> 32)),         0.f),
                fmaxf(__uint_as_float((uint)(a1 & 0xffffffffu)), 0.f),
                fmaxf(__uint_as_float((uint)(a1 >> 32)),         0.f));
            reinterpret_cast<float4*>(ob + (size_t)(o0 + j) * HW_)[lane] = v;
        }
    }
}

// ---------------- launcher ----------------------------------------------------
extern "C" void kernel_launch(void* const* d_in, const int* in_sizes, int n_in,
                              void* d_out, int out_size) {
    const float* feat   = (const float*)d_in[0];
    const float* mask   = (const float*)d_in[1];
    const float* conv_w = (const float*)d_in[2];
    const float* conv_b = (const float*)d_in[3];
    const float* gamma  = (const float*)d_in[4];
    const float* beta   = (const float*)d_in[5];
    float* out = (float*)d_out;

    kstats<<<dim3(KS_CHUNKS, B_), 384>>>(mask);
    kprep1<<<B_, 256>>>(feat, conv_w);
    kred<<<B_, 256>>>();
    kprep2<<<1, 256>>>(conv_b, gamma, beta);
    kmain<<<KM_NBLK, 256>>>(mask, out);
}

// round 7
// speedup vs baseline: 1.4586x; 1.1088x over previous
#include <cuda_runtime.h>
#include <cstdint>

#define B_  8
#define C_  21
#define D_  64
#define O_  128
#define HW_ 65536
#define N_TOT (B_ * HW_)

typedef unsigned long long ull;
typedef unsigned int uint;

#define FFMA2(acc, a, b) asm("fma.rn.f32x2 %0, %1, %2, %0;" : "+l"(acc) : "l"(a), "l"(b))
#define FADD2(acc, a)    asm("add.rn.f32x2 %0, %0, %1;"     : "+l"(acc) : "l"(a))

// ---------------- device scratch ---------------------------------------------
#define KS_CHUNKS 64
#define NVAL 462                      // 441 gram + 21 sums
__device__ float g_Gp[KS_CHUNKS * B_ * NVAL];   // per-block stat partials
__device__ float g_W2T[B_ * C_ * O_];           // combined weights [b][c][o]
__device__ float g_partY[B_ * O_];              // per-batch sumY partials
__device__ float g_partQ[B_ * O_];              // per-batch sumQ partials
__device__ float g_alpha[O_];                   // BN scale
__device__ ull   g_A2[B_ * C_ * O_];            // alpha*W2, f32x2-dup, [b][c][o]
__device__ ull   g_bias2[O_];                   // fused bias, f32x2-dup

// ---------------- cp.async helpers -------------------------------------------
__device__ __forceinline__ void cp16(void* dst, const void* src) {
    uint s = (uint)__cvta_generic_to_shared(dst);
    asm volatile("cp.async.cg.shared.global [%0], [%1], 16;" :: "r"(s), "l"(src));
}
#define CP_COMMIT() asm volatile("cp.async.commit_group;" ::: "memory")
#define CP_WAIT1()  asm volatile("cp.async.wait_group 1;" ::: "memory")
#define CP_WAIT0()  asm volatile("cp.async.wait_group 0;" ::: "memory")

__device__ __forceinline__ float pairsum(ull a) {
    return __uint_as_float((uint)(a & 0xffffffffu)) + __uint_as_float((uint)(a >> 32));
}
__device__ __forceinline__ ull lo64(float4 v) {
    return ((ull)__float_as_uint(v.y) << 32) | __float_as_uint(v.x);
}
__device__ __forceinline__ ull hi64(float4 v) {
    return ((ull)__float_as_uint(v.w) << 32) | __float_as_uint(v.z);
}

// ---------------- kstats: streaming LDG Gram, no smem, no spills -------------
// grid (64, 8): x = 1024-px chunk, y = batch. 384 threads = 12 warps.
// Warp w<9 owns rows {2w, 2w+1}; w in [9,12) owns row {18+(w-9)}.
__global__ __launch_bounds__(384) void kstats(const float* __restrict__ mask) {
    const int b = blockIdx.y;
    const int chunk = blockIdx.x;
    const int tid = threadIdx.x;
    const int wid = tid >> 5;
    const int lane = tid & 31;
    const int nr = (wid < 9) ? 2 : 1;
    const int r0 = (wid < 9) ? wid * 2 : 18 + (wid - 9);

    const float* mb = mask + (size_t)b * C_ * HW_ + chunk * 1024;

    ull acc[2][C_];
    ull ss[2] = {0ull, 0ull};
#pragma unroll
    for (int i = 0; i < 2; i++)
#pragma unroll
        for (int c = 0; c < C_; c++) acc[i][c] = 0ull;

#pragma unroll 1
    for (int it = 0; it < 8; it++) {
        const int q = it * 32 + lane;
        float4 r0v = reinterpret_cast<const float4*>(mb + (size_t)(r0) * HW_)[q];
        ull mr0a = lo64(r0v), mr0b = hi64(r0v);
        FADD2(ss[0], mr0a); FADD2(ss[0], mr0b);
        ull mr1a = 0, mr1b = 0;
        if (nr == 2) {
            float4 r1v = reinterpret_cast<const float4*>(mb + (size_t)(r0 + 1) * HW_)[q];
            mr1a = lo64(r1v); mr1b = hi64(r1v);
            FADD2(ss[1], mr1a); FADD2(ss[1], mr1b);
        }
#pragma unroll
        for (int c = 0; c < C_; c++) {
            float4 v = reinterpret_cast<const float4*>(mb + (size_t)c * HW_)[q];
            ull va = lo64(v), vb = hi64(v);
            FFMA2(acc[0][c], mr0a, va);
            FFMA2(acc[0][c], mr0b, vb);
            if (nr == 2) {
                FFMA2(acc[1][c], mr1a, va);
                FFMA2(acc[1][c], mr1b, vb);
            }
        }
    }

    float* gp = g_Gp + (chunk * B_ + b) * NVAL;
#pragma unroll
    for (int i = 0; i < 2; i++) {
        if (i < nr) {
#pragma unroll
            for (int c = 0; c < C_; c++) {
                float v = pairsum(acc[i][c]);
#pragma unroll
                for (int off = 16; off; off >>= 1) v += __shfl_xor_sync(0xffffffffu, v, off);
                if (lane == 0) gp[(r0 + i) * C_ + c] = v;
            }
            float v = pairsum(ss[i]);
#pragma unroll
            for (int off = 16; off; off >>= 1) v += __shfl_xor_sync(0xffffffffu, v, off);
            if (lane == 0) gp[441 + r0 + i] = v;
        }
    }
}

// ---------------- kprep1: W2T[b][c][o] = <conv_w[o,:], feat[b,c,:]> ----------
__global__ __launch_bounds__(256) void kprep1(const float* __restrict__ feat,
                                              const float* __restrict__ conv_w) {
    __shared__ float sWT[D_ * 129 + 32];
    __shared__ float sF[C_ * D_];
    const int b = blockIdx.x;
    const int tid = threadIdx.x;

    for (int i = tid; i < O_ * D_; i += 256) {
        int o = i >> 6, d = i & 63;
        sWT[d * 129 + o] = conv_w[i];
    }
    for (int i = tid; i < C_ * D_; i += 256) sF[i] = feat[b * C_ * D_ + i];
    __syncthreads();

    for (int idx = tid; idx < C_ * O_; idx += 256) {
        int c = idx >> 7, o = idx & 127;
        float s = 0.f;
#pragma unroll
        for (int d = 0; d < D_; d++)
            s = fmaf(sWT[d * 129 + o], sF[c * D_ + d], s);
        g_W2T[b * C_ * O_ + idx] = s;
    }
}

// ---------------- kprep2a: per-batch partial quadratic forms ------------------
// grid (8): block b reduces its 64 chunk-partials then computes
// sumY_b[o], sumQ_b[o] for all 128 o (thread = o). 256 threads.
__global__ __launch_bounds__(256) void kprep2a() {
    __shared__ float sG[441];
    __shared__ float sS[C_];
    const int b = blockIdx.x;
    const int tid = threadIdx.x;

    // reduce 64 chunk-partials for this batch (coalesced over v)
    for (int v = tid; v < NVAL; v += 256) {
        float s = 0.f;
#pragma unroll
        for (int ch = 0; ch < KS_CHUNKS; ch++) s += g_Gp[(ch * B_ + b) * NVAL + v];
        if (v < 441) sG[v] = s;
        else         sS[v - 441] = s;
    }
    __syncthreads();

    if (tid < O_) {
        const int o = tid;
        float w[C_];
#pragma unroll
        for (int c = 0; c < C_; c++) w[c] = g_W2T[(b * C_ + c) * O_ + o];   // coalesced
        float sumY = 0.f;
#pragma unroll
        for (int c = 0; c < C_; c++) sumY = fmaf(w[c], sS[c], sumY);
        float sumQ = 0.f;
#pragma unroll
        for (int c = 0; c < C_; c++) {
            float t = 0.f;
#pragma unroll
            for (int c2 = 0; c2 < C_; c2++)
                t = fmaf(w[c2], sG[c * C_ + c2], t);     // broadcast smem reads
            sumQ = fmaf(w[c], t, sumQ);
        }
        g_partY[b * O_ + o] = sumY;
        g_partQ[b * O_ + o] = sumQ;
    }
}

// ---------------- kprep2b: combine partials, alpha + fused bias ---------------
__global__ __launch_bounds__(128) void kprep2b(const float* __restrict__ conv_b,
                                               const float* __restrict__ gamma,
                                               const float* __restrict__ beta) {
    const int o = threadIdx.x;
    float sumY = 0.f, sumQ = 0.f;
#pragma unroll
    for (int b = 0; b < B_; b++) {
        sumY += g_partY[b * O_ + o];
        sumQ += g_partQ[b * O_ + o];
    }
    const float invN = 1.f / (float)N_TOT;
    const float b0 = conv_b[o];
    const float es = sumY * invN;
    const float mean = b0 + es;
    const float ey2 = sumQ * invN + 2.f * b0 * es + b0 * b0;
    const float var = ey2 - mean * mean;
    const float alpha = gamma[o] * rsqrtf(var + 1e-5f);
    g_alpha[o] = alpha;
    const float bias2 = beta[o] + alpha * (b0 - mean);
    const uint ub = __float_as_uint(bias2);
    g_bias2[o] = ((ull)ub << 32) | ub;
}

// ---------------- kprep3: A2 = alpha * W2T, f32x2-duplicated ------------------
// grid (8), 256 threads, fully coalesced
__global__ __launch_bounds__(256) void kprep3() {
    __shared__ float sa[O_];
    const int b = blockIdx.x;
    const int tid = threadIdx.x;
    if (tid < O_) sa[tid] = g_alpha[tid];
    __syncthreads();
    for (int i = tid; i < C_ * O_; i += 256) {
        float v = sa[i & 127] * g_W2T[b * C_ * O_ + i];
        uint uv = __float_as_uint(v);
        g_A2[b * C_ * O_ + i] = ((ull)uv << 32) | uv;
    }
}

// ---------------- kmain: persistent fused K=21 GEMM + BN + ReLU --------------
// 296 blocks x 256 threads (2 blocks/SM). Subtile = 128 px x 128 ch.
// Warp = 16 channels; thread = 1 quad (4 px) x 16 channels.
#define KM_NBLK 296
#define KM_NT   4096
#define KM_PX   128

__global__ __launch_bounds__(256) void kmain(const float* __restrict__ mask,
                                             float* __restrict__ out) {
    __shared__ ull sA2[C_ * O_];                       // 21504 B
    __shared__ ull sBias[O_];                          // 1024 B
    __shared__ __align__(16) float sM[2][C_][KM_PX];   // 21504 B (44 KB total)

    const int tid = threadIdx.x;
    const int wid = tid >> 5;
    const int lane = tid & 31;
    const int o0 = wid * 16;

    const int bid = blockIdx.x;
    const int t0 = (bid * KM_NT) / KM_NBLK;
    const int t1 = ((bid + 1) * KM_NT) / KM_NBLK;

    if (tid < O_) sBias[tid] = g_bias2[tid];

    auto issue = [&](int s, int buf) {
        const int b = s >> 9;
        const int px = (s & 511) * KM_PX;
        const float* mb = mask + (size_t)b * C_ * HW_ + px;
        for (int u = tid; u < C_ * (KM_PX / 4); u += 256) {
            int c = u >> 5, q = u & 31;
            cp16(&sM[buf][c][q * 4], mb + (size_t)c * HW_ + q * 4);
        }
        CP_COMMIT();
    };
    auto stage = [&](int b) {
        for (int i = tid; i < C_ * O_; i += 256) sA2[i] = g_A2[b * C_ * O_ + i];
    };

    int curb = t0 >> 9;
    issue(t0, 0);
    stage(curb);

#pragma unroll 1
    for (int s = t0; s < t1; s++) {
        const int buf = (s - t0) & 1;
        if (s + 1 < t1) { issue(s + 1, buf ^ 1); CP_WAIT1(); } else { CP_WAIT0(); }
        const int b = s >> 9;
        if (b != curb) { __syncthreads(); stage(b); curb = b; }
        __syncthreads();

        ull acc[16][2];
#pragma unroll
        for (int j = 0; j < 16; j++) {
            ull bv = sBias[o0 + j];
            acc[j][0] = bv; acc[j][1] = bv;
        }

#pragma unroll
        for (int c = 0; c < C_; c++) {
            ulonglong2 mq = reinterpret_cast<const ulonglong2*>(sM[buf][c])[lane];
            const ulonglong2* cfp = reinterpret_cast<const ulonglong2*>(&sA2[c * O_ + o0]);
#pragma unroll
            for (int k = 0; k < 8; k++) {
                ulonglong2 cf = cfp[k];      // warp-uniform broadcast LDS.128
                FFMA2(acc[2 * k][0],     cf.x, mq.x);
                FFMA2(acc[2 * k][1],     cf.x, mq.y);
                FFMA2(acc[2 * k + 1][0], cf.y, mq.x);
                FFMA2(acc[2 * k + 1][1], cf.y, mq.y);
            }
        }
        __syncthreads();

        const int px = (s & 511) * KM_PX;
        float* ob = out + (size_t)b * O_ * HW_ + px;
#pragma unroll
        for (int j = 0; j < 16; j++) {
            ull a0 = acc[j][0], a1 = acc[j][1];
            float4 v = make_float4(
                fmaxf(__uint_as_float((uint)(a0 & 0xffffffffu)), 0.f),
                fmaxf(__uint_as_float((uint)(a0 >> 32)),         0.f),
                fmaxf(__uint_as_float((uint)(a1 & 0xffffffffu)), 0.f),
                fmaxf(__uint_as_float((uint)(a1 >> 32)),         0.f));
            reinterpret_cast<float4*>(ob + (size_t)(o0 + j) * HW_)[lane] = v;
        }
    }
}

// ---------------- launcher ----------------------------------------------------
extern "C" void kernel_launch(void* const* d_in, const int* in_sizes, int n_in,
                              void* d_out, int out_size) {
    const float* feat   = (const float*)d_in[0];
    const float* mask   = (const float*)d_in[1];
    const float* conv_w = (const float*)d_in[2];
    const float* conv_b = (const float*)d_in[3];
    const float* gamma  = (const float*)d_in[4];
    const float* beta   = (const float*)d_in[5];
    float* out = (float*)d_out;

    kstats<<<dim3(KS_CHUNKS, B_), 384>>>(mask);
    kprep1<<<B_, 256>>>(feat, conv_w);
    kprep2a<<<B_, 256>>>();
    kprep2b<<<1, 128>>>(conv_b, gamma, beta);
    kprep3<<<B_, 256>>>();
    kmain<<<KM_NBLK, 256>>>(mask, out);
}

// round 8
// speedup vs baseline: 1.6994x; 1.1651x over previous
#include <cuda_runtime.h>
#include <cstdint>

#define B_  8
#define C_  21
#define D_  64
#define O_  128
#define HW_ 65536
#define N_TOT (B_ * HW_)

typedef unsigned long long ull;
typedef unsigned int uint;

#define FFMA2(acc, a, b) asm("fma.rn.f32x2 %0, %1, %2, %0;" : "+l"(acc) : "l"(a), "l"(b))
#define FADD2(acc, a)    asm("add.rn.f32x2 %0, %0, %1;"     : "+l"(acc) : "l"(a))

// ---------------- device scratch ---------------------------------------------
#define KS_CHUNKS 74
#define NVAL 252                      // 231 triangle + 21 sums
__device__ float g_Gp[KS_CHUNKS * B_ * NVAL];   // per-block stat partials
__device__ float g_W2T[B_ * C_ * O_];           // combined weights [b][c][o]
__device__ float g_partY[B_ * O_];
__device__ float g_partQ[B_ * O_];
__device__ ull   g_A2[B_ * C_ * O_];            // alpha*W2, f32x2-dup, [b][c][o]
__device__ ull   g_bias2[O_];                   // fused bias, f32x2-dup

// ---------------- helpers ------------------------------------------------------
__device__ __forceinline__ void cp16(void* dst, const void* src) {
    uint s = (uint)__cvta_generic_to_shared(dst);
    asm volatile("cp.async.cg.shared.global [%0], [%1], 16;" :: "r"(s), "l"(src));
}
#define CP_COMMIT() asm volatile("cp.async.commit_group;" ::: "memory")
#define CP_WAIT1()  asm volatile("cp.async.wait_group 1;" ::: "memory")
#define CP_WAIT0()  asm volatile("cp.async.wait_group 0;" ::: "memory")

__device__ __forceinline__ float pairsum(ull a) {
    return __uint_as_float((uint)(a & 0xffffffffu)) + __uint_as_float((uint)(a >> 32));
}
__device__ __forceinline__ ull lo64(float4 v) {
    return ((ull)__float_as_uint(v.y) << 32) | __float_as_uint(v.x);
}
__device__ __forceinline__ ull hi64(float4 v) {
    return ((ull)__float_as_uint(v.w) << 32) | __float_as_uint(v.z);
}
__device__ __forceinline__ float wredsum(float v) {
#pragma unroll
    for (int off = 16; off; off >>= 1) v += __shfl_xor_sync(0xffffffffu, v, off);
    return v;
}

// ---------------- kstats: symmetric (triangular) Gram, LDG streaming ---------
// grid (74, 8), 352 threads = 11 warps, 2 blocks/SM (exactly 2 waves).
// Warp w<10 owns row pair (w, 20-w); warp 10 owns row 10.
// Only lower triangle G[r][c], c<=r is computed: 231 + 21 sums per block.
template <int LO, int HI>
__device__ __forceinline__ void gram_warp(const float* __restrict__ mb,
                                          int u0, int u1, int lane,
                                          float* __restrict__ gp) {
    constexpr bool SGL = (LO == HI);
    constexpr int TRI_LO = LO * (LO + 1) / 2;
    constexpr int TRI_HI = HI * (HI + 1) / 2;

    ull accH[HI + 1];
    ull accL[SGL ? 1 : LO + 1];
    ull sL = 0ull, sH = 0ull;
#pragma unroll
    for (int c = 0; c <= HI; c++) accH[c] = 0ull;
    if (!SGL) {
#pragma unroll
        for (int c = 0; c <= LO; c++) accL[c] = 0ull;
    }

#pragma unroll 1
    for (int u = u0; u < u1; u++) {
        const int q = u * 32 + lane;    // float4 index within batch row
        float4 vH = reinterpret_cast<const float4*>(mb + (size_t)HI * HW_)[q];
        ull mrHa = lo64(vH), mrHb = hi64(vH);
        FADD2(sH, mrHa); FADD2(sH, mrHb);
        ull mrLa = 0, mrLb = 0;
        if (!SGL) {
            float4 vL = reinterpret_cast<const float4*>(mb + (size_t)LO * HW_)[q];
            mrLa = lo64(vL); mrLb = hi64(vL);
            FADD2(sL, mrLa); FADD2(sL, mrLb);
        }
#pragma unroll
        for (int c = 0; c <= HI; c++) {
            ull va, vb;
            if (c == HI)              { va = mrHa; vb = mrHb; }
            else if (!SGL && c == LO) { va = mrLa; vb = mrLb; }
            else {
                float4 v = reinterpret_cast<const float4*>(mb + (size_t)c * HW_)[q];
                va = lo64(v); vb = hi64(v);
            }
            FFMA2(accH[c], mrHa, va);
            FFMA2(accH[c], mrHb, vb);
            if (!SGL && c <= LO) {
                FFMA2(accL[c], mrLa, va);
                FFMA2(accL[c], mrLb, vb);
            }
        }
    }

    // reduce + write triangle partials (row-exclusive, no atomics)
#pragma unroll
    for (int c = 0; c <= HI; c++) {
        float v = wredsum(pairsum(accH[c]));
        if (lane == 0) gp[TRI_HI + c] = v;
    }
    {
        float v = wredsum(pairsum(sH));
        if (lane == 0) gp[231 + HI] = v;
    }
    if (!SGL) {
#pragma unroll
        for (int c = 0; c <= LO; c++) {
            float v = wredsum(pairsum(accL[c]));
            if (lane == 0) gp[TRI_LO + c] = v;
        }
        float v = wredsum(pairsum(sL));
        if (lane == 0) gp[231 + LO] = v;
    }
}

__global__ __launch_bounds__(352, 2) void kstats(const float* __restrict__ mask) {
    const int b = blockIdx.y;
    const int bidx = blockIdx.x;
    const int wid = threadIdx.x >> 5;
    const int lane = threadIdx.x & 31;

    const int u0 = (bidx * 512) / KS_CHUNKS;         // 128-px units in [0,512)
    const int u1 = ((bidx + 1) * 512) / KS_CHUNKS;

    const float* mb = mask + (size_t)b * C_ * HW_;
    float* gp = g_Gp + (bidx * B_ + b) * NVAL;

    switch (wid) {
        case 0:  gram_warp<0, 20>(mb, u0, u1, lane, gp); break;
        case 1:  gram_warp<1, 19>(mb, u0, u1, lane, gp); break;
        case 2:  gram_warp<2, 18>(mb, u0, u1, lane, gp); break;
        case 3:  gram_warp<3, 17>(mb, u0, u1, lane, gp); break;
        case 4:  gram_warp<4, 16>(mb, u0, u1, lane, gp); break;
        case 5:  gram_warp<5, 15>(mb, u0, u1, lane, gp); break;
        case 6:  gram_warp<6, 14>(mb, u0, u1, lane, gp); break;
        case 7:  gram_warp<7, 13>(mb, u0, u1, lane, gp); break;
        case 8:  gram_warp<8, 12>(mb, u0, u1, lane, gp); break;
        case 9:  gram_warp<9, 11>(mb, u0, u1, lane, gp); break;
        default: gram_warp<10, 10>(mb, u0, u1, lane, gp); break;
    }
}

// ---------------- kprep_a: W2T + partial reduce + quadratic forms -------------
// grid (8), 256 threads
__global__ __launch_bounds__(256) void kprep_a(const float* __restrict__ feat,
                                               const float* __restrict__ conv_w) {
    __shared__ float sWT[D_ * 129 + 32];   // transposed weights, padded
    __shared__ float sF[C_ * D_];
    __shared__ float sG[231];
    __shared__ float sS[C_];
    const int b = blockIdx.x;
    const int tid = threadIdx.x;

    // stage weights (transposed) + features
    for (int i = tid; i < O_ * D_; i += 256) {
        int o = i >> 6, d = i & 63;
        sWT[d * 129 + o] = conv_w[i];
    }
    for (int i = tid; i < C_ * D_; i += 256) sF[i] = feat[b * C_ * D_ + i];
    // reduce the 74 chunk-partials for this batch
    for (int v = tid; v < NVAL; v += 256) {
        float s = 0.f;
#pragma unroll
        for (int ch = 0; ch < KS_CHUNKS; ch++) s += g_Gp[(ch * B_ + b) * NVAL + v];
        if (v < 231) sG[v] = s;
        else         sS[v - 231] = s;
    }
    __syncthreads();

    // W2T[b][c][o]
    for (int idx = tid; idx < C_ * O_; idx += 256) {
        int c = idx >> 7, o = idx & 127;
        float s = 0.f;
#pragma unroll
        for (int d = 0; d < D_; d++)
            s = fmaf(sWT[d * 129 + o], sF[c * D_ + d], s);
        g_W2T[b * C_ * O_ + idx] = s;
    }
    __syncthreads();

    // quadratic forms via symmetric triangle
    if (tid < O_) {
        const int o = tid;
        float w[C_];
#pragma unroll
        for (int c = 0; c < C_; c++) w[c] = g_W2T[(b * C_ + c) * O_ + o];
        float sumY = 0.f;
#pragma unroll
        for (int c = 0; c < C_; c++) sumY = fmaf(w[c], sS[c], sumY);
        float sumQ = 0.f;
#pragma unroll
        for (int r = 0; r < C_; r++) {
            const int tr = r * (r + 1) / 2;
            float t = sG[tr + r] * w[r];
#pragma unroll
            for (int c = 0; c < r; c++) t = fmaf(2.f * sG[tr + c], w[c], t);
            sumQ = fmaf(w[r], t, sumQ);
        }
        g_partY[b * O_ + o] = sumY;
        g_partQ[b * O_ + o] = sumQ;
    }
}

// ---------------- kprep_b: alpha/bias (redundant per block) + A2 scaling -----
// grid (8), 128 threads; block b scales batch b's coefficients
__global__ __launch_bounds__(128) void kprep_b(const float* __restrict__ conv_b,
                                               const float* __restrict__ gamma,
                                               const float* __restrict__ beta) {
    const int b = blockIdx.x;
    const int o = threadIdx.x;

    float sumY = 0.f, sumQ = 0.f;
#pragma unroll
    for (int bb = 0; bb < B_; bb++) {
        sumY += g_partY[bb * O_ + o];
        sumQ += g_partQ[bb * O_ + o];
    }
    const float invN = 1.f / (float)N_TOT;
    const float b0 = conv_b[o];
    const float es = sumY * invN;
    const float mean = b0 + es;
    const float ey2 = sumQ * invN + 2.f * b0 * es + b0 * b0;
    const float var = ey2 - mean * mean;
    const float alpha = gamma[o] * rsqrtf(var + 1e-5f);

    if (b == 0) {
        const float bias2 = beta[o] + alpha * (b0 - mean);
        const uint ub = __float_as_uint(bias2);
        g_bias2[o] = ((ull)ub << 32) | ub;
    }
#pragma unroll
    for (int c = 0; c < C_; c++) {
        const int idx = b * C_ * O_ + c * O_ + o;
        float v = alpha * g_W2T[idx];
        uint uv = __float_as_uint(v);
        g_A2[idx] = ((ull)uv << 32) | uv;
    }
}

// ---------------- kmain: persistent fused K=21 GEMM + BN + ReLU --------------
// 148 blocks x 256 threads (1 block/SM). Subtile = 256 px x 128 ch.
// Warp = 16 channels x 256 px; thread = 2 quads (8 px) x 16 ch (acc 64 ull).
// Coefficients via warp-uniform LDG (L1-hot); mask via cp.async double buffer.
// Per (warp,c): 2 mask LDS.128 + 8 uniform LDG.128 = 16 wf vs 64 FFMA2.
#define KM_NBLK 148
#define KM_NT   2048        // 8 b * 256 subtiles of 256 px
#define KM_PX   256

__global__ __launch_bounds__(256) void kmain(const float* __restrict__ mask,
                                             float* __restrict__ out) {
    __shared__ __align__(16) float sM[2][C_][KM_PX];   // 43008 B

    const int tid = threadIdx.x;
    const int wid = tid >> 5;
    const int lane = tid & 31;
    const int o0 = wid * 16;

    const int bid = blockIdx.x;
    const int t0 = (bid * KM_NT) / KM_NBLK;
    const int t1 = ((bid + 1) * KM_NT) / KM_NBLK;

    // hoist fused bias into registers (batch-independent)
    ull bias[16];
#pragma unroll
    for (int j = 0; j < 16; j++) bias[j] = g_bias2[o0 + j];

    auto issue = [&](int s, int buf) {
        const int b = s >> 8;
        const int px = (s & 255) * KM_PX;
        const float* mb = mask + (size_t)b * C_ * HW_ + px;
        for (int u = tid; u < C_ * (KM_PX / 4); u += 256) {   // 1344 16B units
            int c = u >> 6, q = u & 63;
            cp16(&sM[buf][c][q * 4], mb + (size_t)c * HW_ + q * 4);
        }
        CP_COMMIT();
    };

    issue(t0, 0);

#pragma unroll 1
    for (int s = t0; s < t1; s++) {
        const int buf = (s - t0) & 1;
        if (s + 1 < t1) { issue(s + 1, buf ^ 1); CP_WAIT1(); } else { CP_WAIT0(); }
        __syncthreads();

        const int b = s >> 8;
        const ull* cfb = g_A2 + ((size_t)b * C_) * O_ + o0;

        ull acc[16][2][2];   // [ch][quad][half]
#pragma unroll
        for (int j = 0; j < 16; j++) {
            acc[j][0][0] = bias[j]; acc[j][0][1] = bias[j];
            acc[j][1][0] = bias[j]; acc[j][1][1] = bias[j];
        }

#pragma unroll
        for (int c = 0; c < C_; c++) {
            ulonglong2 mq0 = reinterpret_cast<const ulonglong2*>(sM[buf][c])[lane];
            ulonglong2 mq1 = reinterpret_cast<const ulonglong2*>(sM[buf][c])[lane + 32];
            const ulonglong2* cfp = reinterpret_cast<const ulonglong2*>(cfb + (size_t)c * O_);
#pragma unroll
            for (int k = 0; k < 8; k++) {
                ulonglong2 cf = cfp[k];      // warp-uniform LDG.128, L1-hot
                FFMA2(acc[2 * k][0][0],     cf.x, mq0.x);
                FFMA2(acc[2 * k][0][1],     cf.x, mq0.y);
                FFMA2(acc[2 * k][1][0],     cf.x, mq1.x);
                FFMA2(acc[2 * k][1][1],     cf.x, mq1.y);
                FFMA2(acc[2 * k + 1][0][0], cf.y, mq0.x);
                FFMA2(acc[2 * k + 1][0][1], cf.y, mq0.y);
                FFMA2(acc[2 * k + 1][1][0], cf.y, mq1.x);
                FFMA2(acc[2 * k + 1][1][1], cf.y, mq1.y);
            }
        }
        __syncthreads();   // all reads of sM[buf] done before refill

        // epilogue: ReLU + STG.128
        const int px = (s & 255) * KM_PX;
        float* ob = out + (size_t)b * O_ * HW_ + px;
#pragma unroll
        for (int j = 0; j < 16; j++) {
            float4* orow = reinterpret_cast<float4*>(ob + (size_t)(o0 + j) * HW_);
#pragma unroll
            for (int qd = 0; qd < 2; qd++) {
                ull a0 = acc[j][qd][0], a1 = acc[j][qd][1];
                float4 v = make_float4(
                    fmaxf(__uint_as_float((uint)(a0 & 0xffffffffu)), 0.f),
                    fmaxf(__uint_as_float((uint)(a0 >> 32)),         0.f),
                    fmaxf(__uint_as_float((uint)(a1 & 0xffffffffu)), 0.f),
                    fmaxf(__uint_as_float((uint)(a1 >> 32)),         0.f));
                orow[lane + qd * 32] = v;
            }
        }
    }
}

// ---------------- launcher ----------------------------------------------------
extern "C" void kernel_launch(void* const* d_in, const int* in_sizes, int n_in,
                              void* d_out, int out_size) {
    const float* feat   = (const float*)d_in[0];
    const float* mask   = (const float*)d_in[1];
    const float* conv_w = (const float*)d_in[2];
    const float* conv_b = (const float*)d_in[3];
    const float* gamma  = (const float*)d_in[4];
    const float* beta   = (const float*)d_in[5];
    float* out = (float*)d_out;

    kstats<<<dim3(KS_CHUNKS, B_), 352>>>(mask);
    kprep_a<<<B_, 256>>>(feat, conv_w);
    kprep_b<<<B_, 128>>>(conv_b, gamma, beta);
    kmain<<<KM_NBLK, 256>>>(mask, out);
}